// round 12
// baseline (speedup 1.0000x reference)
#include <cuda_runtime.h>
#include <cuda_bf16.h>
#include <cstdint>

// Problem constants
#define NTOT 100000
#define ETOT 1600000
#define GTOT 1024
#define NB   782
#define BN_EPS 1e-5f
#define CAP  64            // padded CSR slots/node (deg~Poisson(16); P(>64)~1e-20)
#define STR  65            // sT row stride (floats)
#define APAD 72            // bf16 tile row stride (144B: 16B-aligned, ldmatrix conflict-free)

// dynamic smem layout (bf16 elements)
#define A_HI_OFF 0
#define A_LO_OFF (128 * APAD)
#define B_HI_OFF (2 * 128 * APAD)
#define B_LO_OFF (2 * 128 * APAD + 64 * APAD)
#define DSMEM_BYTES ((2 * 128 * APAD + 2 * 64 * APAD) * 2)   // 55296

// ---------------- device scratch ----------------
__device__ float g_bufA[NTOT * 64];
__device__ float g_bufB[NTOT * 64];
__device__ float g_agg[NTOT * 64];
__device__ int   g_deg[NTOT];
__device__ int   g_csr[NTOT * CAP];
__device__ float g_stats[NB * 128];
__device__ float g_scale[5 * 64];
__device__ float g_shift[5 * 64];
__device__ float g_pooled[GTOT * 320];
__device__ int   g_cnt[GTOT];
__device__ int   g_done;   // last-block counter (0 between launches)
// pre-transposed + bf16-split weights: [mat][n][k]; mats: 0=W1b, 1/3/5/7=Wa(l), 2/4/6/8=Wb(l)
__device__ __align__(16) __nv_bfloat16 g_WtHi[9 * 4096];
__device__ __align__(16) __nv_bfloat16 g_WtLo[9 * 4096];

// ---------------- helpers ----------------
__device__ __forceinline__ uint32_t s2u(const void* p) {
    uint32_t a;
    asm("{ .reg .u64 t; cvta.to.shared.u64 t, %1; cvt.u32.u64 %0, t; }" : "=r"(a) : "l"(p));
    return a;
}
__device__ __forceinline__ uint32_t pack2bf(float a, float b) {
    __nv_bfloat162 p = __halves2bfloat162(__float2bfloat16_rn(a), __float2bfloat16_rn(b));
    return *reinterpret_cast<uint32_t*>(&p);
}
__device__ __forceinline__ float bfres(float x) {
    return x - __bfloat162float(__float2bfloat16_rn(x));
}
__device__ __forceinline__ void ldm4(uint32_t* r, uint32_t addr) {
    asm volatile("ldmatrix.sync.aligned.m8n8.x4.shared.b16 {%0,%1,%2,%3}, [%4];"
        : "=r"(r[0]), "=r"(r[1]), "=r"(r[2]), "=r"(r[3]) : "r"(addr));
}
__device__ __forceinline__ void mma16816(float* c, const uint32_t* a, const uint32_t* b) {
    asm volatile("mma.sync.aligned.m16n8k16.row.col.f32.bf16.bf16.f32 "
        "{%0,%1,%2,%3}, {%4,%5,%6,%7}, {%8,%9}, {%0,%1,%2,%3};"
        : "+f"(c[0]), "+f"(c[1]), "+f"(c[2]), "+f"(c[3])
        : "r"(a[0]), "r"(a[1]), "r"(a[2]), "r"(a[3]), "r"(b[0]), "r"(b[1]));
}

// ---------------- init: zero + q = x@W1a + W transpose/split prep ----------------
#define GIN_BLKS (NTOT / 4)
#define WPREP_BLKS 144     // 9*4096/256
__global__ void init_kernel(const float* __restrict__ x, const float* __restrict__ W1a,
                            const float* __restrict__ W1b, const float* __restrict__ Wa,
                            const float* __restrict__ Wb) {
    if (blockIdx.x < GIN_BLKS) {
        __shared__ float sW[11 * 64];
        __shared__ float sx[4][12];
        int t = threadIdx.x;
        int nl = t >> 6, c = t & 63;
        int node = blockIdx.x * 4 + nl;
        for (int i = t; i < 11 * 64; i += 256) sW[i] = W1a[i];
        if (t < 44) {
            int n2 = t / 11, k = t % 11;
            int nn = blockIdx.x * 4 + n2;
            sx[n2][k] = (nn < NTOT) ? x[nn * 11 + k] : 0.f;
        }
        __syncthreads();
        if (node < NTOT) {
            float a = 0.f;
#pragma unroll
            for (int k = 0; k < 11; k++) a = fmaf(sx[nl][k], sW[k * 64 + c], a);
            g_bufA[node * 64 + c] = a;
        }
    } else if (blockIdx.x < GIN_BLKS + 256) {
        int b = blockIdx.x - GIN_BLKS;
        int i0 = b * 256 + threadIdx.x;
        int str = 256 * 256;
        for (int i = i0; i < GTOT * 320; i += str) g_pooled[i] = 0.f;
        for (int i = i0; i < NTOT; i += str) g_deg[i] = 0;
        for (int i = i0; i < GTOT; i += str) g_cnt[i] = 0;
    } else {
        int e = (blockIdx.x - GIN_BLKS - 256) * 256 + threadIdx.x;  // 0..36863
        int mat = e >> 12, r = e & 4095, n = r >> 6, k = r & 63;
        float w;
        if (mat == 0)      w = W1b[k * 64 + n];
        else if (mat & 1)  w = Wa[((mat - 1) >> 1) * 4096 + k * 64 + n];
        else               w = Wb[((mat - 2) >> 1) * 4096 + k * 64 + n];
        __nv_bfloat16 h = __float2bfloat16_rn(w);
        g_WtHi[e] = h;
        g_WtLo[e] = __float2bfloat16_rn(w - __bfloat162float(h));
    }
}

// ---------------- scatter: padded-CSR build + graph-size histogram ----------------
__global__ void scatter_kernel(const int* __restrict__ src, const int* __restrict__ dst,
                               const int* __restrict__ batch) {
    int i = blockIdx.x * blockDim.x + threadIdx.x;
    if (i < ETOT) {
        int d = dst[i];
        int c = atomicAdd(&g_deg[d], 1);
        g_csr[(size_t)d * CAP + c] = src[i];
    }
    if (i < NTOT) atomicAdd(&g_cnt[batch[i]], 1);
}

// ---------------- aggregation (warp/node, shfl-broadcast) ----------------
template <bool FIRST>
__global__ void agg_kernel(const float* __restrict__ ba, int layer) {
    const float* hin = (layer & 1) ? g_bufB : g_bufA;
    int t = threadIdx.x, lane = t & 31;
    int gw = (blockIdx.x * blockDim.x + t) >> 5;
    int nwarps = (gridDim.x * blockDim.x) >> 5;

    float c0, c1, d0 = 0.f, d1 = 0.f;
    if (FIRST) {
        c0 = __ldg(&ba[2 * lane]); c1 = __ldg(&ba[2 * lane + 1]);
    } else {
        float2 sc = *(const float2*)(g_scale + (layer - 1) * 64 + 2 * lane);
        float2 sh = *(const float2*)(g_shift + (layer - 1) * 64 + 2 * lane);
        c0 = sc.x; c1 = sc.y; d0 = sh.x; d1 = sh.y;
    }

    for (int node = gw; node < NTOT; node += nwarps) {
        float2 own = *(const float2*)(hin + (size_t)node * 64 + 2 * lane);
        float ax = own.x, ay = own.y;
        int dg = __ldg(&g_deg[node]);
        int s0 = node * CAP, s1 = s0 + dg;
        for (int e = s0; e < s1; e += 32) {
            int m = s1 - e; if (m > 32) m = 32;
            int idx = (lane < m) ? __ldg(g_csr + e + lane) : 0;
#pragma unroll 4
            for (int ee = 0; ee < m; ++ee) {
                int s = __shfl_sync(0xffffffffu, idx, ee);
                float2 v = *(const float2*)(hin + (size_t)s * 64 + 2 * lane);
                ax += v.x; ay += v.y;
            }
        }
        if (FIRST) {
            ax = fmaxf(ax + c0, 0.f);
            ay = fmaxf(ay + c1, 0.f);
        } else {
            float kk = (float)(dg + 1);
            ax = fmaf(c0, ax, kk * d0);
            ay = fmaf(c1, ay, kk * d1);
        }
        *(float2*)(g_agg + (size_t)node * 64 + 2 * lane) = make_float2(ax, ay);
    }
}

// ---------------- GEMM via mma.sync bf16 3-term split (paired B ldmatrix.x4) ----------------
// Block: 128 nodes, 8 warps; warp w owns rows w*16..+15.
// B x4 load: lanes 0-15 -> n-rows (np*16 .. +7) k/k+8 halves; lanes 16-31 -> n-rows +8..+15.
// Result regs {r0,r1} = frag for nt=2np, {r2,r3} = frag for nt=2np+1.
__device__ __forceinline__ void warp_gemm(float acc[8][4],
                                          uint32_t AhiB, uint32_t AloB,
                                          uint32_t BhiB, uint32_t BloB,
                                          int m0, int lane) {
    int rA = m0 + (lane & 7) + ((lane >> 3) & 1) * 8;
    int cA = ((lane >> 4) & 1) * 8;
    int rB = (lane & 7) + ((lane >> 4) << 3);
    int cB = ((lane >> 3) & 1) * 8;
#pragma unroll
    for (int ks = 0; ks < 4; ks++) {
        int k = ks * 16;
        uint32_t ah[4], al[4];
        ldm4(ah, AhiB + (uint32_t)(rA * APAD + k + cA) * 2);
        ldm4(al, AloB + (uint32_t)(rA * APAD + k + cA) * 2);
#pragma unroll
        for (int np = 0; np < 4; np++) {
            uint32_t boff = (uint32_t)((np * 16 + rB) * APAD + k + cB) * 2;
            uint32_t bh[4], bl[4];
            ldm4(bh, BhiB + boff);
            ldm4(bl, BloB + boff);
            mma16816(acc[2 * np],     ah, bh);
            mma16816(acc[2 * np],     ah, bl);
            mma16816(acc[2 * np],     al, bh);
            mma16816(acc[2 * np + 1], ah, bh + 2);
            mma16816(acc[2 * np + 1], ah, bl + 2);
            mma16816(acc[2 * np + 1], al, bh + 2);
        }
    }
}

template <bool FIRST>
__global__ void gemm_kernel(int mat1, int mat2,
                            const float* __restrict__ ba, const float* __restrict__ bb,
                            const int* __restrict__ batch,
                            const float* __restrict__ gamma_l, const float* __restrict__ beta_l,
                            int layer) {
    extern __shared__ __align__(16) char dsm[];
    __nv_bfloat16* Ahi = (__nv_bfloat16*)dsm + A_HI_OFF;
    __nv_bfloat16* Alo = (__nv_bfloat16*)dsm + A_LO_OFF;
    __nv_bfloat16* Bhi = (__nv_bfloat16*)dsm + B_HI_OFF;
    __nv_bfloat16* Blo = (__nv_bfloat16*)dsm + B_LO_OFF;
    float* sT = (float*)dsm;                 // alias A region; used after all MMA reads done

    __shared__ float sBa[64];
    __shared__ float sBb[64];
    __shared__ int   sBatch[128];
    __shared__ int   sLast;

    float* hout = (layer & 1) ? g_bufA : g_bufB;
    int t = threadIdx.x, wid = t >> 5, lane = t & 31;
    int base = blockIdx.x * 128;
    uint32_t AhiB = s2u(Ahi), AloB = s2u(Alo), BhiB = s2u(Bhi), BloB = s2u(Blo);

    if (t < 64) { sBb[t] = bb[t]; if (!FIRST) sBa[t] = ba[t]; }
    if (t < 128) { int n = base + t; sBatch[t] = (n < NTOT) ? batch[n] : -1; }

    // stage A (bf16 hi/lo) from g_agg
    for (int i = t; i < 2048; i += 256) {
        int row = i >> 4, q = i & 15;
        float4 v = make_float4(0.f, 0.f, 0.f, 0.f);
        if (base + row < NTOT) v = *(const float4*)(g_agg + (size_t)(base + row) * 64 + q * 4);
        uint32_t off = (uint32_t)(row * APAD + q * 4) * 2;
        *(uint2*)((char*)Ahi + off) = make_uint2(pack2bf(v.x, v.y), pack2bf(v.z, v.w));
        *(uint2*)((char*)Alo + off) =
            make_uint2(pack2bf(bfres(v.x), bfres(v.y)), pack2bf(bfres(v.z), bfres(v.w)));
    }
    // stage B for first MMA (FIRST -> mat2 is the only GEMM)
    {
        int mat = FIRST ? mat2 : mat1;
        for (int i = t; i < 512; i += 256) {
            int n = i >> 3, kc = i & 7;
            uint32_t off = (uint32_t)(n * APAD + kc * 8) * 2;
            *(uint4*)((char*)Bhi + off) = *(const uint4*)(g_WtHi + mat * 4096 + n * 64 + kc * 8);
            *(uint4*)((char*)Blo + off) = *(const uint4*)(g_WtLo + mat * 4096 + n * 64 + kc * 8);
        }
    }
    __syncthreads();

    int m0 = wid * 16;
    int r1 = m0 + (lane >> 2), r2 = r1 + 8;
    int cb = (lane & 3) * 2;
    float acc[8][4];
#pragma unroll
    for (int nt = 0; nt < 8; nt++)
#pragma unroll
        for (int j = 0; j < 4; j++) acc[nt][j] = 0.f;

    warp_gemm(acc, AhiB, AloB, BhiB, BloB, m0, lane);

    if (!FIRST) {
        // restage t1 = ReLU(acc + ba) into A tiles (warp-local rows: no sync needed)
#pragma unroll
        for (int nt = 0; nt < 8; nt++) {
            int col = nt * 8 + cb;
            float v0 = fmaxf(acc[nt][0] + sBa[col], 0.f);
            float v1 = fmaxf(acc[nt][1] + sBa[col + 1], 0.f);
            float v2 = fmaxf(acc[nt][2] + sBa[col], 0.f);
            float v3 = fmaxf(acc[nt][3] + sBa[col + 1], 0.f);
            *(uint32_t*)((char*)Ahi + (uint32_t)(r1 * APAD + col) * 2) = pack2bf(v0, v1);
            *(uint32_t*)((char*)Alo + (uint32_t)(r1 * APAD + col) * 2) = pack2bf(bfres(v0), bfres(v1));
            *(uint32_t*)((char*)Ahi + (uint32_t)(r2 * APAD + col) * 2) = pack2bf(v2, v3);
            *(uint32_t*)((char*)Alo + (uint32_t)(r2 * APAD + col) * 2) = pack2bf(bfres(v2), bfres(v3));
            acc[nt][0] = acc[nt][1] = acc[nt][2] = acc[nt][3] = 0.f;
        }
        __syncthreads();   // B1 reads complete before B2 overwrite
        for (int i = t; i < 512; i += 256) {
            int n = i >> 3, kc = i & 7;
            uint32_t off = (uint32_t)(n * APAD + kc * 8) * 2;
            *(uint4*)((char*)Bhi + off) = *(const uint4*)(g_WtHi + mat2 * 4096 + n * 64 + kc * 8);
            *(uint4*)((char*)Blo + off) = *(const uint4*)(g_WtLo + mat2 * 4096 + n * 64 + kc * 8);
        }
        __syncthreads();
        warp_gemm(acc, AhiB, AloB, BhiB, BloB, m0, lane);
    }

    __syncthreads();       // all MMA smem reads done before sT alias writes
#pragma unroll
    for (int nt = 0; nt < 8; nt++) {
        int col = nt * 8 + cb;
        sT[r1 * STR + col]     = fmaxf(acc[nt][0] + sBb[col], 0.f);
        sT[r1 * STR + col + 1] = fmaxf(acc[nt][1] + sBb[col + 1], 0.f);
        sT[r2 * STR + col]     = fmaxf(acc[nt][2] + sBb[col], 0.f);
        sT[r2 * STR + col + 1] = fmaxf(acc[nt][3] + sBb[col + 1], 0.f);
    }
    __syncthreads();

    // epilogue: store h, stats partials, pooled run-length atomics
    int ty = t >> 4, tx = t & 15;
    float ssum[4] = {0.f, 0.f, 0.f, 0.f};
    float sqr[4]  = {0.f, 0.f, 0.f, 0.f};
    float run[4]  = {0.f, 0.f, 0.f, 0.f};
    int curg = -1;
#pragma unroll
    for (int i = 0; i < 8; i++) {
        int r = ty * 8 + i;
        int node = base + r;
        if (node < NTOT) {
            float v[4];
#pragma unroll
            for (int j = 0; j < 4; j++) {
                v[j] = sT[r * STR + tx * 4 + j];
                ssum[j] += v[j];
                sqr[j]   = fmaf(v[j], v[j], sqr[j]);
            }
            *(float4*)(hout + (size_t)node * 64 + tx * 4) = make_float4(v[0], v[1], v[2], v[3]);
            int g = sBatch[r];
            if (g != curg) {
                if (curg >= 0) {
#pragma unroll
                    for (int j = 0; j < 4; j++)
                        atomicAdd(&g_pooled[curg * 320 + layer * 64 + tx * 4 + j], run[j]);
                }
                curg = g;
#pragma unroll
                for (int j = 0; j < 4; j++) run[j] = v[j];
            } else {
#pragma unroll
                for (int j = 0; j < 4; j++) run[j] += v[j];
            }
        }
    }
    if (curg >= 0) {
#pragma unroll
        for (int j = 0; j < 4; j++)
            atomicAdd(&g_pooled[curg * 320 + layer * 64 + tx * 4 + j], run[j]);
    }

    __syncthreads();
#pragma unroll
    for (int j = 0; j < 4; j++) {
        sT[ty * 64 + tx * 4 + j]        = ssum[j];
        sT[1024 + ty * 64 + tx * 4 + j] = sqr[j];
    }
    __syncthreads();
    if (t < 64) {
        float S = 0.f, Q = 0.f;
#pragma unroll
        for (int i2 = 0; i2 < 16; i2++) {
            S += sT[i2 * 64 + t];
            Q += sT[1024 + i2 * 64 + t];
        }
        g_stats[blockIdx.x * 128 + t]      = S;
        g_stats[blockIdx.x * 128 + 64 + t] = Q;
    }

    // ---- fused BN-stats finalize (last block computes scale/shift) ----
    __syncthreads();
    if (t == 0) {
        __threadfence();
        int old = atomicAdd(&g_done, 1);
        sLast = (old == NB - 1) ? 1 : 0;
    }
    __syncthreads();
    if (sLast) {
        __threadfence();
        int c = t & 63, part = t >> 6;      // 4 partial sums per channel
        float S = 0.f, Q = 0.f;
        for (int b = part; b < NB; b += 4) {
            S += g_stats[b * 128 + c];
            Q += g_stats[b * 128 + 64 + c];
        }
        __syncthreads();
        sT[part * 64 + c]       = S;
        sT[256 + part * 64 + c] = Q;
        __syncthreads();
        if (t < 64) {
            float Sf = sT[t] + sT[64 + t] + sT[128 + t] + sT[192 + t];
            float Qf = sT[256 + t] + sT[320 + t] + sT[384 + t] + sT[448 + t];
            float mean = Sf / (float)NTOT;
            float var  = Qf / (float)NTOT - mean * mean;
            float rstd = rsqrtf(var + BN_EPS);
            float sc = rstd * gamma_l[t];
            g_scale[layer * 64 + t] = sc;
            g_shift[layer * 64 + t] = beta_l[t] - mean * sc;
        }
        __syncthreads();
        if (t == 0) { __threadfence(); g_done = 0; }
    }
}

// ---------------- MLP head ----------------
__global__ void mlp_kernel(const float* __restrict__ fc1W, const float* __restrict__ fc1b,
                           const float* __restrict__ fc2W, const float* __restrict__ fc2b,
                           float* __restrict__ out) {
    __shared__ float z[320];
    __shared__ float red[2];
    int g = blockIdx.x, t = threadIdx.x;
    float cg = (float)g_cnt[g];
    for (int k = t; k < 320; k += 64)
        z[k] = fmaf(g_scale[k], g_pooled[g * 320 + k], cg * g_shift[k]);
    __syncthreads();
    float acc = fc1b[t];
    for (int k = 0; k < 320; k++)
        acc = fmaf(z[k], fc1W[k * 64 + t], acc);
    float h = fmaxf(acc, 0.f) * fc2W[t];
    for (int off = 16; off; off >>= 1) h += __shfl_down_sync(0xffffffffu, h, off);
    if ((t & 31) == 0) red[t >> 5] = h;
    __syncthreads();
    if (t == 0) out[g] = red[0] + red[1] + fc2b[0];
}

// ---------------- host launcher ----------------
extern "C" void kernel_launch(void* const* d_in, const int* in_sizes, int n_in,
                              void* d_out, int out_size) {
    const float* x     = (const float*)d_in[0];
    const int*   ei    = (const int*)d_in[1];
    const int*   batch = (const int*)d_in[2];
    const float* W1a   = (const float*)d_in[3];
    const float* b1a   = (const float*)d_in[4];
    const float* W1b   = (const float*)d_in[5];
    const float* b1b   = (const float*)d_in[6];
    const float* Wa    = (const float*)d_in[7];
    const float* ba    = (const float*)d_in[8];
    const float* Wb    = (const float*)d_in[9];
    const float* bb    = (const float*)d_in[10];
    const float* gamma = (const float*)d_in[11];
    const float* beta  = (const float*)d_in[12];
    const float* fc1W  = (const float*)d_in[13];
    const float* fc1b  = (const float*)d_in[14];
    const float* fc2W  = (const float*)d_in[15];
    const float* fc2b  = (const float*)d_in[16];
    float* out = (float*)d_out;

    const int* srcp = ei;
    const int* dstp = ei + ETOT;

    cudaFuncSetAttribute(gemm_kernel<true>,  cudaFuncAttributeMaxDynamicSharedMemorySize, DSMEM_BYTES);
    cudaFuncSetAttribute(gemm_kernel<false>, cudaFuncAttributeMaxDynamicSharedMemorySize, DSMEM_BYTES);

    init_kernel<<<GIN_BLKS + 256 + WPREP_BLKS, 256>>>(x, W1a, W1b, Wa, Wb);
    scatter_kernel<<<(ETOT + 255) / 256, 256>>>(srcp, dstp, batch);

    // layer 0 (single GEMM: W1b; bias b1a folded into aggregation)
    agg_kernel<true><<<1184, 256>>>(b1a, 0);
    gemm_kernel<true><<<NB, 256, DSMEM_BYTES>>>(0, 0, nullptr, b1b, batch, gamma, beta, 0);

    for (int l = 1; l < 5; l++) {
        agg_kernel<false><<<1184, 256>>>(nullptr, l);
        gemm_kernel<false><<<NB, 256, DSMEM_BYTES>>>(2 * l - 1, 2 * l,
                                                     ba + (l - 1) * 64, bb + (l - 1) * 64,
                                                     batch, gamma + l * 64, beta + l * 64, l);
    }

    mlp_kernel<<<GTOT, 64>>>(fc1W, fc1b, fc2W, fc2b, out);
}

// round 13
// speedup vs baseline: 1.1176x; 1.1176x over previous
#include <cuda_runtime.h>
#include <cuda_bf16.h>
#include <cstdint>

// Problem constants
#define NTOT 100000
#define ETOT 1600000
#define GTOT 1024
#define NB   782
#define BN_EPS 1e-5f
#define CAP  64            // padded CSR slots/node (deg~Poisson(16); P(>64)~1e-20)
#define STR  65            // sT row stride (floats)
#define APAD 72            // bf16 tile row stride (144B: 16B-aligned, ldmatrix conflict-free)

// dynamic smem layout (bf16 elements)
#define A_HI_OFF 0
#define A_LO_OFF (128 * APAD)
#define B_HI_OFF (2 * 128 * APAD)
#define B_LO_OFF (2 * 128 * APAD + 64 * APAD)
#define DSMEM_BYTES ((2 * 128 * APAD + 2 * 64 * APAD) * 2)   // 55296

// ---------------- device scratch ----------------
__device__ float g_bufA[NTOT * 64];
__device__ float g_bufB[NTOT * 64];
__device__ float g_agg[NTOT * 64];
__device__ int   g_deg[NTOT];
__device__ int   g_csr[NTOT * CAP];
__device__ float g_stats[NB * 128];
__device__ float g_scale[5 * 64];
__device__ float g_shift[5 * 64];
__device__ float g_pooled[GTOT * 320];
__device__ int   g_cnt[GTOT];
// pre-transposed + bf16-split weights: [mat][n][k]; mats: 0=W1b, 1/3/5/7=Wa(l), 2/4/6/8=Wb(l)
__device__ __align__(16) __nv_bfloat16 g_WtHi[9 * 4096];
__device__ __align__(16) __nv_bfloat16 g_WtLo[9 * 4096];

// ---------------- helpers ----------------
__device__ __forceinline__ uint32_t s2u(const void* p) {
    uint32_t a;
    asm("{ .reg .u64 t; cvta.to.shared.u64 t, %1; cvt.u32.u64 %0, t; }" : "=r"(a) : "l"(p));
    return a;
}
__device__ __forceinline__ uint32_t pack2bf(float a, float b) {
    __nv_bfloat162 p = __halves2bfloat162(__float2bfloat16_rn(a), __float2bfloat16_rn(b));
    return *reinterpret_cast<uint32_t*>(&p);
}
__device__ __forceinline__ float bfres(float x) {
    return x - __bfloat162float(__float2bfloat16_rn(x));
}
__device__ __forceinline__ void ldm4(uint32_t* r, uint32_t addr) {
    asm volatile("ldmatrix.sync.aligned.m8n8.x4.shared.b16 {%0,%1,%2,%3}, [%4];"
        : "=r"(r[0]), "=r"(r[1]), "=r"(r[2]), "=r"(r[3]) : "r"(addr));
}
__device__ __forceinline__ void mma16816(float* c, const uint32_t* a, const uint32_t* b) {
    asm volatile("mma.sync.aligned.m16n8k16.row.col.f32.bf16.bf16.f32 "
        "{%0,%1,%2,%3}, {%4,%5,%6,%7}, {%8,%9}, {%0,%1,%2,%3};"
        : "+f"(c[0]), "+f"(c[1]), "+f"(c[2]), "+f"(c[3])
        : "r"(a[0]), "r"(a[1]), "r"(a[2]), "r"(a[3]), "r"(b[0]), "r"(b[1]));
}

// ---------------- init: zero + q = x@W1a + W transpose/split prep ----------------
#define GIN_BLKS (NTOT / 4)
#define WPREP_BLKS 144     // 9*4096/256
__global__ void init_kernel(const float* __restrict__ x, const float* __restrict__ W1a,
                            const float* __restrict__ W1b, const float* __restrict__ Wa,
                            const float* __restrict__ Wb) {
    if (blockIdx.x < GIN_BLKS) {
        __shared__ float sW[11 * 64];
        __shared__ float sx[4][12];
        int t = threadIdx.x;
        int nl = t >> 6, c = t & 63;
        int node = blockIdx.x * 4 + nl;
        for (int i = t; i < 11 * 64; i += 256) sW[i] = W1a[i];
        if (t < 44) {
            int n2 = t / 11, k = t % 11;
            int nn = blockIdx.x * 4 + n2;
            sx[n2][k] = (nn < NTOT) ? x[nn * 11 + k] : 0.f;
        }
        __syncthreads();
        if (node < NTOT) {
            float a = 0.f;
#pragma unroll
            for (int k = 0; k < 11; k++) a = fmaf(sx[nl][k], sW[k * 64 + c], a);
            g_bufA[node * 64 + c] = a;
        }
    } else if (blockIdx.x < GIN_BLKS + 256) {
        int b = blockIdx.x - GIN_BLKS;
        int i0 = b * 256 + threadIdx.x;
        int str = 256 * 256;
        for (int i = i0; i < GTOT * 320; i += str) g_pooled[i] = 0.f;
        for (int i = i0; i < NTOT; i += str) g_deg[i] = 0;
        for (int i = i0; i < GTOT; i += str) g_cnt[i] = 0;
    } else {
        int e = (blockIdx.x - GIN_BLKS - 256) * 256 + threadIdx.x;  // 0..36863
        int mat = e >> 12, r = e & 4095, n = r >> 6, k = r & 63;
        float w;
        if (mat == 0)      w = W1b[k * 64 + n];
        else if (mat & 1)  w = Wa[((mat - 1) >> 1) * 4096 + k * 64 + n];
        else               w = Wb[((mat - 2) >> 1) * 4096 + k * 64 + n];
        __nv_bfloat16 h = __float2bfloat16_rn(w);
        g_WtHi[e] = h;
        g_WtLo[e] = __float2bfloat16_rn(w - __bfloat162float(h));
    }
}

// ---------------- scatter: padded-CSR build + graph-size histogram ----------------
__global__ void scatter_kernel(const int* __restrict__ src, const int* __restrict__ dst,
                               const int* __restrict__ batch) {
    int i = blockIdx.x * blockDim.x + threadIdx.x;
    if (i < ETOT) {
        int d = dst[i];
        int c = atomicAdd(&g_deg[d], 1);
        g_csr[(size_t)d * CAP + c] = src[i];
    }
    if (i < NTOT) atomicAdd(&g_cnt[batch[i]], 1);
}

// ---------------- aggregation (warp/node, shfl-broadcast) ----------------
template <bool FIRST>
__global__ void agg_kernel(const float* __restrict__ ba, int layer) {
    const float* hin = (layer & 1) ? g_bufB : g_bufA;
    int t = threadIdx.x, lane = t & 31;
    int gw = (blockIdx.x * blockDim.x + t) >> 5;
    int nwarps = (gridDim.x * blockDim.x) >> 5;

    float c0, c1, d0 = 0.f, d1 = 0.f;
    if (FIRST) {
        c0 = __ldg(&ba[2 * lane]); c1 = __ldg(&ba[2 * lane + 1]);
    } else {
        float2 sc = *(const float2*)(g_scale + (layer - 1) * 64 + 2 * lane);
        float2 sh = *(const float2*)(g_shift + (layer - 1) * 64 + 2 * lane);
        c0 = sc.x; c1 = sc.y; d0 = sh.x; d1 = sh.y;
    }

    for (int node = gw; node < NTOT; node += nwarps) {
        float2 own = *(const float2*)(hin + (size_t)node * 64 + 2 * lane);
        float ax = own.x, ay = own.y;
        int dg = __ldg(&g_deg[node]);
        int s0 = node * CAP, s1 = s0 + dg;
        for (int e = s0; e < s1; e += 32) {
            int m = s1 - e; if (m > 32) m = 32;
            int idx = (lane < m) ? __ldg(g_csr + e + lane) : 0;
#pragma unroll 4
            for (int ee = 0; ee < m; ++ee) {
                int s = __shfl_sync(0xffffffffu, idx, ee);
                float2 v = *(const float2*)(hin + (size_t)s * 64 + 2 * lane);
                ax += v.x; ay += v.y;
            }
        }
        if (FIRST) {
            ax = fmaxf(ax + c0, 0.f);
            ay = fmaxf(ay + c1, 0.f);
        } else {
            float kk = (float)(dg + 1);
            ax = fmaf(c0, ax, kk * d0);
            ay = fmaf(c1, ay, kk * d1);
        }
        *(float2*)(g_agg + (size_t)node * 64 + 2 * lane) = make_float2(ax, ay);
    }
}

// ---------------- GEMM via mma.sync bf16 3-term split (paired B ldmatrix.x4) ----------------
// Block: 128 nodes, 8 warps; warp w owns rows w*16..+15.
// B x4 load: lanes 0-15 -> n-rows (np*16 .. +7) k/k+8 halves; lanes 16-31 -> n-rows +8..+15.
// Result regs {r0,r1} = frag for nt=2np, {r2,r3} = frag for nt=2np+1.
__device__ __forceinline__ void warp_gemm(float acc[8][4],
                                          uint32_t AhiB, uint32_t AloB,
                                          uint32_t BhiB, uint32_t BloB,
                                          int m0, int lane) {
    int rA = m0 + (lane & 7) + ((lane >> 3) & 1) * 8;
    int cA = ((lane >> 4) & 1) * 8;
    int rB = (lane & 7) + ((lane >> 4) << 3);
    int cB = ((lane >> 3) & 1) * 8;
#pragma unroll
    for (int ks = 0; ks < 4; ks++) {
        int k = ks * 16;
        uint32_t ah[4], al[4];
        ldm4(ah, AhiB + (uint32_t)(rA * APAD + k + cA) * 2);
        ldm4(al, AloB + (uint32_t)(rA * APAD + k + cA) * 2);
#pragma unroll
        for (int np = 0; np < 4; np++) {
            uint32_t boff = (uint32_t)((np * 16 + rB) * APAD + k + cB) * 2;
            uint32_t bh[4], bl[4];
            ldm4(bh, BhiB + boff);
            ldm4(bl, BloB + boff);
            mma16816(acc[2 * np],     ah, bh);
            mma16816(acc[2 * np],     ah, bl);
            mma16816(acc[2 * np],     al, bh);
            mma16816(acc[2 * np + 1], ah, bh + 2);
            mma16816(acc[2 * np + 1], ah, bl + 2);
            mma16816(acc[2 * np + 1], al, bh + 2);
        }
    }
}

template <bool FIRST>
__global__ void gemm_kernel(int mat1, int mat2,
                            const float* __restrict__ ba, const float* __restrict__ bb,
                            const int* __restrict__ batch, int layer) {
    extern __shared__ __align__(16) char dsm[];
    __nv_bfloat16* Ahi = (__nv_bfloat16*)dsm + A_HI_OFF;
    __nv_bfloat16* Alo = (__nv_bfloat16*)dsm + A_LO_OFF;
    __nv_bfloat16* Bhi = (__nv_bfloat16*)dsm + B_HI_OFF;
    __nv_bfloat16* Blo = (__nv_bfloat16*)dsm + B_LO_OFF;
    float* sT = (float*)dsm;                 // alias A region; used after all MMA reads done

    __shared__ float sBa[64];
    __shared__ float sBb[64];
    __shared__ int   sBatch[128];

    float* hout = (layer & 1) ? g_bufA : g_bufB;
    int t = threadIdx.x, wid = t >> 5, lane = t & 31;
    int base = blockIdx.x * 128;
    uint32_t AhiB = s2u(Ahi), AloB = s2u(Alo), BhiB = s2u(Bhi), BloB = s2u(Blo);

    if (t < 64) { sBb[t] = bb[t]; if (!FIRST) sBa[t] = ba[t]; }
    if (t < 128) { int n = base + t; sBatch[t] = (n < NTOT) ? batch[n] : -1; }

    // stage A (bf16 hi/lo) from g_agg
    for (int i = t; i < 2048; i += 256) {
        int row = i >> 4, q = i & 15;
        float4 v = make_float4(0.f, 0.f, 0.f, 0.f);
        if (base + row < NTOT) v = *(const float4*)(g_agg + (size_t)(base + row) * 64 + q * 4);
        uint32_t off = (uint32_t)(row * APAD + q * 4) * 2;
        *(uint2*)((char*)Ahi + off) = make_uint2(pack2bf(v.x, v.y), pack2bf(v.z, v.w));
        *(uint2*)((char*)Alo + off) =
            make_uint2(pack2bf(bfres(v.x), bfres(v.y)), pack2bf(bfres(v.z), bfres(v.w)));
    }
    // stage B for first MMA (FIRST -> mat2 is the only GEMM)
    {
        int mat = FIRST ? mat2 : mat1;
        for (int i = t; i < 512; i += 256) {
            int n = i >> 3, kc = i & 7;
            uint32_t off = (uint32_t)(n * APAD + kc * 8) * 2;
            *(uint4*)((char*)Bhi + off) = *(const uint4*)(g_WtHi + mat * 4096 + n * 64 + kc * 8);
            *(uint4*)((char*)Blo + off) = *(const uint4*)(g_WtLo + mat * 4096 + n * 64 + kc * 8);
        }
    }
    __syncthreads();

    int m0 = wid * 16;
    int r1 = m0 + (lane >> 2), r2 = r1 + 8;
    int cb = (lane & 3) * 2;
    float acc[8][4];
#pragma unroll
    for (int nt = 0; nt < 8; nt++)
#pragma unroll
        for (int j = 0; j < 4; j++) acc[nt][j] = 0.f;

    warp_gemm(acc, AhiB, AloB, BhiB, BloB, m0, lane);

    if (!FIRST) {
        // restage t1 = ReLU(acc + ba) into A tiles (warp-local rows: no sync needed)
#pragma unroll
        for (int nt = 0; nt < 8; nt++) {
            int col = nt * 8 + cb;
            float v0 = fmaxf(acc[nt][0] + sBa[col], 0.f);
            float v1 = fmaxf(acc[nt][1] + sBa[col + 1], 0.f);
            float v2 = fmaxf(acc[nt][2] + sBa[col], 0.f);
            float v3 = fmaxf(acc[nt][3] + sBa[col + 1], 0.f);
            *(uint32_t*)((char*)Ahi + (uint32_t)(r1 * APAD + col) * 2) = pack2bf(v0, v1);
            *(uint32_t*)((char*)Alo + (uint32_t)(r1 * APAD + col) * 2) = pack2bf(bfres(v0), bfres(v1));
            *(uint32_t*)((char*)Ahi + (uint32_t)(r2 * APAD + col) * 2) = pack2bf(v2, v3);
            *(uint32_t*)((char*)Alo + (uint32_t)(r2 * APAD + col) * 2) = pack2bf(bfres(v2), bfres(v3));
            acc[nt][0] = acc[nt][1] = acc[nt][2] = acc[nt][3] = 0.f;
        }
        __syncthreads();   // B1 reads complete before B2 overwrite
        for (int i = t; i < 512; i += 256) {
            int n = i >> 3, kc = i & 7;
            uint32_t off = (uint32_t)(n * APAD + kc * 8) * 2;
            *(uint4*)((char*)Bhi + off) = *(const uint4*)(g_WtHi + mat2 * 4096 + n * 64 + kc * 8);
            *(uint4*)((char*)Blo + off) = *(const uint4*)(g_WtLo + mat2 * 4096 + n * 64 + kc * 8);
        }
        __syncthreads();
        warp_gemm(acc, AhiB, AloB, BhiB, BloB, m0, lane);
    }

    __syncthreads();       // all MMA smem reads done before sT alias writes
#pragma unroll
    for (int nt = 0; nt < 8; nt++) {
        int col = nt * 8 + cb;
        sT[r1 * STR + col]     = fmaxf(acc[nt][0] + sBb[col], 0.f);
        sT[r1 * STR + col + 1] = fmaxf(acc[nt][1] + sBb[col + 1], 0.f);
        sT[r2 * STR + col]     = fmaxf(acc[nt][2] + sBb[col], 0.f);
        sT[r2 * STR + col + 1] = fmaxf(acc[nt][3] + sBb[col + 1], 0.f);
    }
    __syncthreads();

    // epilogue: store h, stats partials, pooled run-length atomics
    int ty = t >> 4, tx = t & 15;
    float ssum[4] = {0.f, 0.f, 0.f, 0.f};
    float sqr[4]  = {0.f, 0.f, 0.f, 0.f};
    float run[4]  = {0.f, 0.f, 0.f, 0.f};
    int curg = -1;
#pragma unroll
    for (int i = 0; i < 8; i++) {
        int r = ty * 8 + i;
        int node = base + r;
        if (node < NTOT) {
            float v[4];
#pragma unroll
            for (int j = 0; j < 4; j++) {
                v[j] = sT[r * STR + tx * 4 + j];
                ssum[j] += v[j];
                sqr[j]   = fmaf(v[j], v[j], sqr[j]);
            }
            *(float4*)(hout + (size_t)node * 64 + tx * 4) = make_float4(v[0], v[1], v[2], v[3]);
            int g = sBatch[r];
            if (g != curg) {
                if (curg >= 0) {
#pragma unroll
                    for (int j = 0; j < 4; j++)
                        atomicAdd(&g_pooled[curg * 320 + layer * 64 + tx * 4 + j], run[j]);
                }
                curg = g;
#pragma unroll
                for (int j = 0; j < 4; j++) run[j] = v[j];
            } else {
#pragma unroll
                for (int j = 0; j < 4; j++) run[j] += v[j];
            }
        }
    }
    if (curg >= 0) {
#pragma unroll
        for (int j = 0; j < 4; j++)
            atomicAdd(&g_pooled[curg * 320 + layer * 64 + tx * 4 + j], run[j]);
    }

    __syncthreads();
#pragma unroll
    for (int j = 0; j < 4; j++) {
        sT[ty * 64 + tx * 4 + j]        = ssum[j];
        sT[1024 + ty * 64 + tx * 4 + j] = sqr[j];
    }
    __syncthreads();
    if (t < 64) {
        float S = 0.f, Q = 0.f;
#pragma unroll
        for (int i2 = 0; i2 < 16; i2++) {
            S += sT[i2 * 64 + t];
            Q += sT[1024 + i2 * 64 + t];
        }
        g_stats[blockIdx.x * 128 + t]      = S;
        g_stats[blockIdx.x * 128 + 64 + t] = Q;
    }
}

// ---------------- BN stats finalize (parallel across 64 blocks) ----------------
__global__ void stats_kernel(const float* __restrict__ gamma_l,
                             const float* __restrict__ beta_l, int layer) {
    int c = blockIdx.x;
    int t = threadIdx.x;
    __shared__ float sS[128], sQ[128];
    float S = 0.f, Q = 0.f;
    for (int b = t; b < NB; b += 128) {
        S += g_stats[b * 128 + c];
        Q += g_stats[b * 128 + 64 + c];
    }
    sS[t] = S; sQ[t] = Q;
    __syncthreads();
    for (int off = 64; off; off >>= 1) {
        if (t < off) { sS[t] += sS[t + off]; sQ[t] += sQ[t + off]; }
        __syncthreads();
    }
    if (t == 0) {
        float mean = sS[0] / (float)NTOT;
        float var  = sQ[0] / (float)NTOT - mean * mean;
        float rstd = rsqrtf(var + BN_EPS);
        float sc = rstd * gamma_l[c];
        g_scale[layer * 64 + c] = sc;
        g_shift[layer * 64 + c] = beta_l[c] - mean * sc;
    }
}

// ---------------- MLP head ----------------
__global__ void mlp_kernel(const float* __restrict__ fc1W, const float* __restrict__ fc1b,
                           const float* __restrict__ fc2W, const float* __restrict__ fc2b,
                           float* __restrict__ out) {
    __shared__ float z[320];
    __shared__ float red[2];
    int g = blockIdx.x, t = threadIdx.x;
    float cg = (float)g_cnt[g];
    for (int k = t; k < 320; k += 64)
        z[k] = fmaf(g_scale[k], g_pooled[g * 320 + k], cg * g_shift[k]);
    __syncthreads();
    float acc = fc1b[t];
    for (int k = 0; k < 320; k++)
        acc = fmaf(z[k], fc1W[k * 64 + t], acc);
    float h = fmaxf(acc, 0.f) * fc2W[t];
    for (int off = 16; off; off >>= 1) h += __shfl_down_sync(0xffffffffu, h, off);
    if ((t & 31) == 0) red[t >> 5] = h;
    __syncthreads();
    if (t == 0) out[g] = red[0] + red[1] + fc2b[0];
}

// ---------------- host launcher ----------------
extern "C" void kernel_launch(void* const* d_in, const int* in_sizes, int n_in,
                              void* d_out, int out_size) {
    const float* x     = (const float*)d_in[0];
    const int*   ei    = (const int*)d_in[1];
    const int*   batch = (const int*)d_in[2];
    const float* W1a   = (const float*)d_in[3];
    const float* b1a   = (const float*)d_in[4];
    const float* W1b   = (const float*)d_in[5];
    const float* b1b   = (const float*)d_in[6];
    const float* Wa    = (const float*)d_in[7];
    const float* ba    = (const float*)d_in[8];
    const float* Wb    = (const float*)d_in[9];
    const float* bb    = (const float*)d_in[10];
    const float* gamma = (const float*)d_in[11];
    const float* beta  = (const float*)d_in[12];
    const float* fc1W  = (const float*)d_in[13];
    const float* fc1b  = (const float*)d_in[14];
    const float* fc2W  = (const float*)d_in[15];
    const float* fc2b  = (const float*)d_in[16];
    float* out = (float*)d_out;

    const int* srcp = ei;
    const int* dstp = ei + ETOT;

    cudaFuncSetAttribute(gemm_kernel<true>,  cudaFuncAttributeMaxDynamicSharedMemorySize, DSMEM_BYTES);
    cudaFuncSetAttribute(gemm_kernel<false>, cudaFuncAttributeMaxDynamicSharedMemorySize, DSMEM_BYTES);

    init_kernel<<<GIN_BLKS + 256 + WPREP_BLKS, 256>>>(x, W1a, W1b, Wa, Wb);
    scatter_kernel<<<(ETOT + 255) / 256, 256>>>(srcp, dstp, batch);

    // layer 0 (single GEMM: W1b; bias b1a folded into aggregation)
    agg_kernel<true><<<1184, 256>>>(b1a, 0);
    gemm_kernel<true><<<NB, 256, DSMEM_BYTES>>>(0, 0, nullptr, b1b, batch, 0);
    stats_kernel<<<64, 128>>>(gamma, beta, 0);

    for (int l = 1; l < 5; l++) {
        agg_kernel<false><<<1184, 256>>>(nullptr, l);
        gemm_kernel<false><<<NB, 256, DSMEM_BYTES>>>(2 * l - 1, 2 * l,
                                                     ba + (l - 1) * 64, bb + (l - 1) * 64,
                                                     batch, l);
        stats_kernel<<<64, 128>>>(gamma + l * 64, beta + l * 64, l);
    }

    mlp_kernel<<<GTOT, 64>>>(fc1W, fc1b, fc2W, fc2b, out);
}

// round 15
// speedup vs baseline: 1.1964x; 1.0705x over previous
#include <cuda_runtime.h>
#include <cuda_bf16.h>
#include <cstdint>

// Problem constants
#define NTOT 100000
#define ETOT 1600000
#define GTOT 1024
#define NB   782
#define BN_EPS 1e-5f
#define CAP  64            // padded CSR slots/node (deg~Poisson(16); P(>64)~1e-20)
#define STR  65            // sT row stride (floats)
#define APAD 72            // bf16 tile row stride (144B: 16B-aligned, ldmatrix conflict-free)
#define AGG_BLKS 1184      // gather blocks in agg kernel (stats blocks appended after)

// dynamic smem layout (bf16 elements)
#define A_HI_OFF 0
#define A_LO_OFF (128 * APAD)
#define B_HI_OFF (2 * 128 * APAD)
#define B_LO_OFF (2 * 128 * APAD + 64 * APAD)
#define DSMEM_BYTES ((2 * 128 * APAD + 2 * 64 * APAD) * 2)   // 55296

// ---------------- device scratch ----------------
__device__ float g_bufA[NTOT * 64];
__device__ float g_bufB[NTOT * 64];
__device__ uint32_t g_aggH[NTOT * 32];    // packed bf16 hi pairs (2 ch / uint32)
__device__ uint32_t g_aggL[NTOT * 32];    // packed bf16 lo (residual) pairs
__device__ int   g_deg[NTOT];
__device__ int   g_csr[NTOT * CAP];
__device__ float g_stats[NB * 128];
__device__ float g_scale[5 * 64];
__device__ float g_shift[5 * 64];
__device__ float g_pooled[GTOT * 320];
__device__ int   g_cnt[GTOT];
__device__ float g_shv[2][64];            // kk-correction vector, double-buffered by layer parity
// GEMM2 weights, pre-transposed + split: mats 0=W1b, 1..4=Wb(layer)
__device__ __align__(16) __nv_bfloat16 g_WtHi[5 * 4096];
__device__ __align__(16) __nv_bfloat16 g_WtLo[5 * 4096];
// GEMM1 weights for current layer: diag(s)*Wa transposed + split (written by agg stats blocks)
__device__ __align__(16) __nv_bfloat16 g_WsHi[4096];
__device__ __align__(16) __nv_bfloat16 g_WsLo[4096];

// ---------------- helpers ----------------
__device__ __forceinline__ uint32_t s2u(const void* p) {
    uint32_t a;
    asm("{ .reg .u64 t; cvta.to.shared.u64 t, %1; cvt.u32.u64 %0, t; }" : "=r"(a) : "l"(p));
    return a;
}
__device__ __forceinline__ uint32_t pack2bf(float a, float b) {
    __nv_bfloat162 p = __halves2bfloat162(__float2bfloat16_rn(a), __float2bfloat16_rn(b));
    return *reinterpret_cast<uint32_t*>(&p);
}
__device__ __forceinline__ float bfres(float x) {
    return x - __bfloat162float(__float2bfloat16_rn(x));
}
__device__ __forceinline__ void ldm4(uint32_t* r, uint32_t addr) {
    asm volatile("ldmatrix.sync.aligned.m8n8.x4.shared.b16 {%0,%1,%2,%3}, [%4];"
        : "=r"(r[0]), "=r"(r[1]), "=r"(r[2]), "=r"(r[3]) : "r"(addr));
}
__device__ __forceinline__ void mma16816(float* c, const uint32_t* a, const uint32_t* b) {
    asm volatile("mma.sync.aligned.m16n8k16.row.col.f32.bf16.bf16.f32 "
        "{%0,%1,%2,%3}, {%4,%5,%6,%7}, {%8,%9}, {%0,%1,%2,%3};"
        : "+f"(c[0]), "+f"(c[1]), "+f"(c[2]), "+f"(c[3])
        : "r"(a[0]), "r"(a[1]), "r"(a[2]), "r"(a[3]), "r"(b[0]), "r"(b[1]));
}

// ---------------- init: zero + q = x@W1a + GEMM2-weight transpose/split prep ----------------
#define GIN_BLKS (NTOT / 4)
#define WPREP_BLKS 80      // 5*4096/256
__global__ void init_kernel(const float* __restrict__ x, const float* __restrict__ W1a,
                            const float* __restrict__ W1b, const float* __restrict__ Wb) {
    if (blockIdx.x < GIN_BLKS) {
        __shared__ float sW[11 * 64];
        __shared__ float sx[4][12];
        int t = threadIdx.x;
        int nl = t >> 6, c = t & 63;
        int node = blockIdx.x * 4 + nl;
        for (int i = t; i < 11 * 64; i += 256) sW[i] = W1a[i];
        if (t < 44) {
            int n2 = t / 11, k = t % 11;
            int nn = blockIdx.x * 4 + n2;
            sx[n2][k] = (nn < NTOT) ? x[nn * 11 + k] : 0.f;
        }
        __syncthreads();
        if (node < NTOT) {
            float a = 0.f;
#pragma unroll
            for (int k = 0; k < 11; k++) a = fmaf(sx[nl][k], sW[k * 64 + c], a);
            g_bufA[node * 64 + c] = a;
        }
    } else if (blockIdx.x < GIN_BLKS + 256) {
        int b = blockIdx.x - GIN_BLKS;
        int i0 = b * 256 + threadIdx.x;
        int str = 256 * 256;
        for (int i = i0; i < GTOT * 320; i += str) g_pooled[i] = 0.f;
        for (int i = i0; i < NTOT; i += str) g_deg[i] = 0;
        for (int i = i0; i < GTOT; i += str) g_cnt[i] = 0;
    } else {
        int e = (blockIdx.x - GIN_BLKS - 256) * 256 + threadIdx.x;  // 0..20479
        int mat = e >> 12, r = e & 4095, n = r >> 6, k = r & 63;
        float w = (mat == 0) ? W1b[k * 64 + n] : Wb[(mat - 1) * 4096 + k * 64 + n];
        __nv_bfloat16 h = __float2bfloat16_rn(w);
        g_WtHi[e] = h;
        g_WtLo[e] = __float2bfloat16_rn(w - __bfloat162float(h));
    }
}

// ---------------- scatter: padded-CSR build + graph-size histogram ----------------
__global__ void scatter_kernel(const int* __restrict__ src, const int* __restrict__ dst,
                               const int* __restrict__ batch) {
    int i = blockIdx.x * blockDim.x + threadIdx.x;
    if (i < ETOT) {
        int d = dst[i];
        int c = atomicAdd(&g_deg[d], 1);
        g_csr[(size_t)d * CAP + c] = src[i];
    }
    if (i < NTOT) atomicAdd(&g_cnt[batch[i]], 1);
}

// ---------------- aggregation: raw GIN sum u = h + sum_j h_j, packed bf16 hi/lo output ----
// FIRST: applies ReLU(u + b1a) (layer0 identity GEMM1 fold). Otherwise raw u (BN folded
// into GEMM1 weights downstream).
// Blocks >= AGG_BLKS (only !FIRST): BN stats finalize for layer-1 + Ws/shv prep (256 thr).
template <bool FIRST>
__global__ void agg_kernel(const float* __restrict__ p0 /*ba for FIRST*/,
                           const float* __restrict__ gamma_l, const float* __restrict__ beta_l,
                           const float* __restrict__ Wa_lm1, int layer) {
    int t = threadIdx.x;
    if (!FIRST && blockIdx.x >= AGG_BLKS) {
        // ---- embedded BN stats finalize (64 blocks, one channel each, 256 threads) ----
        __shared__ float sS[256], sQ[256];
        __shared__ float s_sc, s_sh;
        int c = blockIdx.x - AGG_BLKS;
        int lm1 = layer - 1;
        float S = 0.f, Q = 0.f;
        for (int b = t; b < NB; b += 256) {
            S += g_stats[b * 128 + c];
            Q += g_stats[b * 128 + 64 + c];
        }
        sS[t] = S; sQ[t] = Q;
        __syncthreads();
        for (int off = 128; off; off >>= 1) {
            if (t < off) { sS[t] += sS[t + off]; sQ[t] += sQ[t + off]; }
            __syncthreads();
        }
        if (t == 0) {
            float mean = sS[0] / (float)NTOT;
            float var  = sQ[0] / (float)NTOT - mean * mean;
            float rstd = rsqrtf(var + BN_EPS);
            float sc = rstd * gamma_l[c];
            float sh = beta_l[c] - mean * sc;
            g_scale[lm1 * 64 + c] = sc;
            g_shift[lm1 * 64 + c] = sh;
            s_sc = sc; s_sh = sh;
        }
        __syncthreads();
        if (t < 64) {
            float wa = Wa_lm1[c * 64 + t];      // Wa[k=c][n=t]
            float w = s_sc * wa;
            __nv_bfloat16 h = __float2bfloat16_rn(w);
            g_WsHi[t * 64 + c] = h;             // transposed [n][k]
            g_WsLo[t * 64 + c] = __float2bfloat16_rn(w - __bfloat162float(h));
            atomicAdd(&g_shv[layer & 1][t], s_sh * wa);
        }
        return;
    }

    const float* hin = (layer & 1) ? g_bufB : g_bufA;
    int lane = t & 31;
    int gw = (blockIdx.x * blockDim.x + t) >> 5;
    int nwarps = (AGG_BLKS * blockDim.x) >> 5;

    float c0 = 0.f, c1 = 0.f;
    if (FIRST) { c0 = __ldg(&p0[2 * lane]); c1 = __ldg(&p0[2 * lane + 1]); }

    for (int node = gw; node < NTOT; node += nwarps) {
        float2 own = *(const float2*)(hin + (size_t)node * 64 + 2 * lane);
        float ax = own.x, ay = own.y;
        int dg = __ldg(&g_deg[node]);
        int s0 = node * CAP, s1 = s0 + dg;
        for (int e = s0; e < s1; e += 32) {
            int m = s1 - e; if (m > 32) m = 32;
            int idx = (lane < m) ? __ldg(g_csr + e + lane) : 0;
#pragma unroll 4
            for (int ee = 0; ee < m; ++ee) {
                int s = __shfl_sync(0xffffffffu, idx, ee);
                float2 v = *(const float2*)(hin + (size_t)s * 64 + 2 * lane);
                ax += v.x; ay += v.y;
            }
        }
        if (FIRST) {
            ax = fmaxf(ax + c0, 0.f);
            ay = fmaxf(ay + c1, 0.f);
        }
        g_aggH[node * 32 + lane] = pack2bf(ax, ay);
        g_aggL[node * 32 + lane] = pack2bf(bfres(ax), bfres(ay));
    }
}

// ---------------- GEMM via mma.sync bf16 3-term split (paired B ldmatrix.x4) ----------------
__device__ __forceinline__ void warp_gemm(float acc[8][4],
                                          uint32_t AhiB, uint32_t AloB,
                                          uint32_t BhiB, uint32_t BloB,
                                          int m0, int lane) {
    int rA = m0 + (lane & 7) + ((lane >> 3) & 1) * 8;
    int cA = ((lane >> 4) & 1) * 8;
    int rB = (lane & 7) + ((lane >> 4) << 3);
    int cB = ((lane >> 3) & 1) * 8;
#pragma unroll
    for (int ks = 0; ks < 4; ks++) {
        int k = ks * 16;
        uint32_t ah[4], al[4];
        ldm4(ah, AhiB + (uint32_t)(rA * APAD + k + cA) * 2);
        ldm4(al, AloB + (uint32_t)(rA * APAD + k + cA) * 2);
#pragma unroll
        for (int np = 0; np < 4; np++) {
            uint32_t boff = (uint32_t)((np * 16 + rB) * APAD + k + cB) * 2;
            uint32_t bh[4], bl[4];
            ldm4(bh, BhiB + boff);
            ldm4(bl, BloB + boff);
            mma16816(acc[2 * np],     ah, bh);
            mma16816(acc[2 * np],     ah, bl);
            mma16816(acc[2 * np],     al, bh);
            mma16816(acc[2 * np + 1], ah, bh + 2);
            mma16816(acc[2 * np + 1], ah, bl + 2);
            mma16816(acc[2 * np + 1], al, bh + 2);
        }
    }
}

template <bool FIRST>
__global__ void gemm_kernel(int mat2,
                            const float* __restrict__ ba, const float* __restrict__ bb,
                            const int* __restrict__ batch, int layer) {
    extern __shared__ __align__(16) char dsm[];
    __nv_bfloat16* Ahi = (__nv_bfloat16*)dsm + A_HI_OFF;
    __nv_bfloat16* Alo = (__nv_bfloat16*)dsm + A_LO_OFF;
    __nv_bfloat16* Bhi = (__nv_bfloat16*)dsm + B_HI_OFF;
    __nv_bfloat16* Blo = (__nv_bfloat16*)dsm + B_LO_OFF;
    float* sT = (float*)dsm;                 // alias A region; used after all MMA reads done

    __shared__ float sBa[64];
    __shared__ float sBb[64];
    __shared__ float sShv[64];
    __shared__ float sKK[128];
    __shared__ int   sBatch[128];

    float* hout = (layer & 1) ? g_bufA : g_bufB;
    int t = threadIdx.x, wid = t >> 5, lane = t & 31;
    int base = blockIdx.x * 128;
    uint32_t AhiB = s2u(Ahi), AloB = s2u(Alo), BhiB = s2u(Bhi), BloB = s2u(Blo);

    if (t < 64) {
        sBb[t] = bb[t];
        if (!FIRST) { sBa[t] = ba[t]; sShv[t] = g_shv[layer & 1][t]; }
    }
    if (t < 128) {
        int n = base + t;
        sBatch[t] = (n < NTOT) ? batch[n] : -1;
        if (!FIRST) sKK[t] = (n < NTOT) ? (float)(g_deg[n] + 1) : 0.f;
    }
    // zero the OTHER shv buffer for the next layer's stats (block 0 only; no concurrent user)
    if (blockIdx.x == 0 && t >= 128 && t < 192) g_shv[(layer + 1) & 1][t - 128] = 0.f;

    // stage A: raw uint4 copy of pre-split packed tiles
    for (int i = t; i < 1024; i += 256) {
        int row = i >> 3, q = i & 7;
        uint4 h4 = make_uint4(0u, 0u, 0u, 0u), l4 = make_uint4(0u, 0u, 0u, 0u);
        if (base + row < NTOT) {
            h4 = *(const uint4*)(g_aggH + (size_t)(base + row) * 32 + q * 4);
            l4 = *(const uint4*)(g_aggL + (size_t)(base + row) * 32 + q * 4);
        }
        *(uint4*)((char*)Ahi + (uint32_t)(row * APAD + q * 8) * 2) = h4;
        *(uint4*)((char*)Alo + (uint32_t)(row * APAD + q * 8) * 2) = l4;
    }
    // stage B for first MMA: FIRST -> g_Wt[0]; else -> g_Ws (scaled Wa)
    for (int i = t; i < 512; i += 256) {
        int n = i >> 3, kc = i & 7;
        uint32_t off = (uint32_t)(n * APAD + kc * 8) * 2;
        if (FIRST) {
            *(uint4*)((char*)Bhi + off) = *(const uint4*)(g_WtHi + n * 64 + kc * 8);
            *(uint4*)((char*)Blo + off) = *(const uint4*)(g_WtLo + n * 64 + kc * 8);
        } else {
            *(uint4*)((char*)Bhi + off) = *(const uint4*)(g_WsHi + n * 64 + kc * 8);
            *(uint4*)((char*)Blo + off) = *(const uint4*)(g_WsLo + n * 64 + kc * 8);
        }
    }
    __syncthreads();

    int m0 = wid * 16;
    int r1 = m0 + (lane >> 2), r2 = r1 + 8;
    int cb = (lane & 3) * 2;
    float acc[8][4];
#pragma unroll
    for (int nt = 0; nt < 8; nt++)
#pragma unroll
        for (int j = 0; j < 4; j++) acc[nt][j] = 0.f;

    warp_gemm(acc, AhiB, AloB, BhiB, BloB, m0, lane);

    if (!FIRST) {
        // restage t1 = ReLU(acc + kk*shv + ba) into A tiles (warp-local rows)
        float kk1 = sKK[r1], kk2 = sKK[r2];
#pragma unroll
        for (int nt = 0; nt < 8; nt++) {
            int col = nt * 8 + cb;
            float v0 = fmaxf(acc[nt][0] + kk1 * sShv[col]     + sBa[col],     0.f);
            float v1 = fmaxf(acc[nt][1] + kk1 * sShv[col + 1] + sBa[col + 1], 0.f);
            float v2 = fmaxf(acc[nt][2] + kk2 * sShv[col]     + sBa[col],     0.f);
            float v3 = fmaxf(acc[nt][3] + kk2 * sShv[col + 1] + sBa[col + 1], 0.f);
            *(uint32_t*)((char*)Ahi + (uint32_t)(r1 * APAD + col) * 2) = pack2bf(v0, v1);
            *(uint32_t*)((char*)Alo + (uint32_t)(r1 * APAD + col) * 2) = pack2bf(bfres(v0), bfres(v1));
            *(uint32_t*)((char*)Ahi + (uint32_t)(r2 * APAD + col) * 2) = pack2bf(v2, v3);
            *(uint32_t*)((char*)Alo + (uint32_t)(r2 * APAD + col) * 2) = pack2bf(bfres(v2), bfres(v3));
            acc[nt][0] = acc[nt][1] = acc[nt][2] = acc[nt][3] = 0.f;
        }
        __syncthreads();   // B1 reads complete before B2 overwrite
        for (int i = t; i < 512; i += 256) {
            int n = i >> 3, kc = i & 7;
            uint32_t off = (uint32_t)(n * APAD + kc * 8) * 2;
            *(uint4*)((char*)Bhi + off) = *(const uint4*)(g_WtHi + mat2 * 4096 + n * 64 + kc * 8);
            *(uint4*)((char*)Blo + off) = *(const uint4*)(g_WtLo + mat2 * 4096 + n * 64 + kc * 8);
        }
        __syncthreads();
        warp_gemm(acc, AhiB, AloB, BhiB, BloB, m0, lane);
    }

    __syncthreads();       // all MMA smem reads done before sT alias writes
#pragma unroll
    for (int nt = 0; nt < 8; nt++) {
        int col = nt * 8 + cb;
        sT[r1 * STR + col]     = fmaxf(acc[nt][0] + sBb[col], 0.f);
        sT[r1 * STR + col + 1] = fmaxf(acc[nt][1] + sBb[col + 1], 0.f);
        sT[r2 * STR + col]     = fmaxf(acc[nt][2] + sBb[col], 0.f);
        sT[r2 * STR + col + 1] = fmaxf(acc[nt][3] + sBb[col + 1], 0.f);
    }
    __syncthreads();

    // epilogue: store h, stats partials, pooled run-length atomics
    int ty = t >> 4, tx = t & 15;
    float ssum[4] = {0.f, 0.f, 0.f, 0.f};
    float sqr[4]  = {0.f, 0.f, 0.f, 0.f};
    float run[4]  = {0.f, 0.f, 0.f, 0.f};
    int curg = -1;
#pragma unroll
    for (int i = 0; i < 8; i++) {
        int r = ty * 8 + i;
        int node = base + r;
        if (node < NTOT) {
            float v[4];
#pragma unroll
            for (int j = 0; j < 4; j++) {
                v[j] = sT[r * STR + tx * 4 + j];
                ssum[j] += v[j];
                sqr[j]   = fmaf(v[j], v[j], sqr[j]);
            }
            *(float4*)(hout + (size_t)node * 64 + tx * 4) = make_float4(v[0], v[1], v[2], v[3]);
            int g = sBatch[r];
            if (g != curg) {
                if (curg >= 0) {
#pragma unroll
                    for (int j = 0; j < 4; j++)
                        atomicAdd(&g_pooled[curg * 320 + layer * 64 + tx * 4 + j], run[j]);
                }
                curg = g;
#pragma unroll
                for (int j = 0; j < 4; j++) run[j] = v[j];
            } else {
#pragma unroll
                for (int j = 0; j < 4; j++) run[j] += v[j];
            }
        }
    }
    if (curg >= 0) {
#pragma unroll
        for (int j = 0; j < 4; j++)
            atomicAdd(&g_pooled[curg * 320 + layer * 64 + tx * 4 + j], run[j]);
    }

    __syncthreads();
#pragma unroll
    for (int j = 0; j < 4; j++) {
        sT[ty * 64 + tx * 4 + j]        = ssum[j];
        sT[1024 + ty * 64 + tx * 4 + j] = sqr[j];
    }
    __syncthreads();
    if (t < 64) {
        float S = 0.f, Q = 0.f;
#pragma unroll
        for (int i2 = 0; i2 < 16; i2++) {
            S += sT[i2 * 64 + t];
            Q += sT[1024 + i2 * 64 + t];
        }
        g_stats[blockIdx.x * 128 + t]      = S;
        g_stats[blockIdx.x * 128 + 64 + t] = Q;
    }
}

// ---------------- BN stats finalize (standalone, layer 4 only) ----------------
__global__ void stats_kernel(const float* __restrict__ gamma_l,
                             const float* __restrict__ beta_l, int layer) {
    int c = blockIdx.x;
    int t = threadIdx.x;  // 128
    __shared__ float sS[128], sQ[128];
    float S = 0.f, Q = 0.f;
    for (int b = t; b < NB; b += 128) {
        S += g_stats[b * 128 + c];
        Q += g_stats[b * 128 + 64 + c];
    }
    sS[t] = S; sQ[t] = Q;
    __syncthreads();
    for (int off = 64; off; off >>= 1) {
        if (t < off) { sS[t] += sS[t + off]; sQ[t] += sQ[t + off]; }
        __syncthreads();
    }
    if (t == 0) {
        float mean = sS[0] / (float)NTOT;
        float var  = sQ[0] / (float)NTOT - mean * mean;
        float rstd = rsqrtf(var + BN_EPS);
        float sc = rstd * gamma_l[c];
        g_scale[layer * 64 + c] = sc;
        g_shift[layer * 64 + c] = beta_l[c] - mean * sc;
    }
}

// ---------------- MLP head ----------------
__global__ void mlp_kernel(const float* __restrict__ fc1W, const float* __restrict__ fc1b,
                           const float* __restrict__ fc2W, const float* __restrict__ fc2b,
                           float* __restrict__ out) {
    __shared__ float z[320];
    __shared__ float red[2];
    int g = blockIdx.x, t = threadIdx.x;
    float cg = (float)g_cnt[g];
    for (int k = t; k < 320; k += 64)
        z[k] = fmaf(g_scale[k], g_pooled[g * 320 + k], cg * g_shift[k]);
    __syncthreads();
    float acc = fc1b[t];
    for (int k = 0; k < 320; k++)
        acc = fmaf(z[k], fc1W[k * 64 + t], acc);
    float h = fmaxf(acc, 0.f) * fc2W[t];
    for (int off = 16; off; off >>= 1) h += __shfl_down_sync(0xffffffffu, h, off);
    if ((t & 31) == 0) red[t >> 5] = h;
    __syncthreads();
    if (t == 0) out[g] = red[0] + red[1] + fc2b[0];
}

// ---------------- host launcher ----------------
extern "C" void kernel_launch(void* const* d_in, const int* in_sizes, int n_in,
                              void* d_out, int out_size) {
    const float* x     = (const float*)d_in[0];
    const int*   ei    = (const int*)d_in[1];
    const int*   batch = (const int*)d_in[2];
    const float* W1a   = (const float*)d_in[3];
    const float* b1a   = (const float*)d_in[4];
    const float* W1b   = (const float*)d_in[5];
    const float* b1b   = (const float*)d_in[6];
    const float* Wa    = (const float*)d_in[7];
    const float* ba    = (const float*)d_in[8];
    const float* Wb    = (const float*)d_in[9];
    const float* bb    = (const float*)d_in[10];
    const float* gamma = (const float*)d_in[11];
    const float* beta  = (const float*)d_in[12];
    const float* fc1W  = (const float*)d_in[13];
    const float* fc1b  = (const float*)d_in[14];
    const float* fc2W  = (const float*)d_in[15];
    const float* fc2b  = (const float*)d_in[16];
    float* out = (float*)d_out;

    const int* srcp = ei;
    const int* dstp = ei + ETOT;

    cudaFuncSetAttribute(gemm_kernel<true>,  cudaFuncAttributeMaxDynamicSharedMemorySize, DSMEM_BYTES);
    cudaFuncSetAttribute(gemm_kernel<false>, cudaFuncAttributeMaxDynamicSharedMemorySize, DSMEM_BYTES);

    init_kernel<<<GIN_BLKS + 256 + WPREP_BLKS, 256>>>(x, W1a, W1b, Wb);
    scatter_kernel<<<(ETOT + 255) / 256, 256>>>(srcp, dstp, batch);

    // layer 0 (single GEMM: W1b; bias b1a folded into aggregation ReLU)
    agg_kernel<true><<<AGG_BLKS, 256>>>(b1a, nullptr, nullptr, nullptr, 0);
    gemm_kernel<true><<<NB, 256, DSMEM_BYTES>>>(0, nullptr, b1b, batch, 0);

    for (int l = 1; l < 5; l++) {
        // agg(l): raw GIN sums + embedded stats(l-1) finalize + Ws/shv prep (64 extra blocks)
        agg_kernel<false><<<AGG_BLKS + 64, 256>>>(nullptr, gamma + (l - 1) * 64,
                                                  beta + (l - 1) * 64, Wa + (l - 1) * 4096, l);
        gemm_kernel<false><<<NB, 256, DSMEM_BYTES>>>(l, ba + (l - 1) * 64, bb + (l - 1) * 64,
                                                     batch, l);
    }

    stats_kernel<<<64, 128>>>(gamma + 4 * 64, beta + 4 * 64, 4);
    mlp_kernel<<<GTOT, 64>>>(fc1W, fc1b, fc2W, fc2b, out);
}